// round 5
// baseline (speedup 1.0000x reference)
#include <cuda_runtime.h>

// CustomStrainEnergyLoss: mean over B of (trapz(y_pred - y_true, x, segments j < idx))^2
// Element-weight form: integral = sum_{j=0}^{idx} w(j) * (p[j]-t[j]),
//   w(j) = 0.5*((j>0 ? x[j]-x[j-1] : 0) + (j<idx ? x[j+1]-x[j] : 0))
// Interior vectors v < (idx>>2): all four lanes have both neighbors in range,
// central-difference weight 0.5*(x[j+1]-x[j-1]) with x[-1] clamped to x[0].
//
// ROUND 5: warp-per-row. One warp owns one row -> per-lane trip count ~32
// (vs ~4 with block-per-row), giving the unroller a real steady state and
// deep MLP. Shuffle-only reduction, no shared memory, no barriers.

#define THREADS 256
#define WPB (THREADS / 32)   // warps per block

__global__ void zero_out_kernel(float* out) {
    out[0] = 0.0f;
}

__global__ __launch_bounds__(THREADS)
void strain_loss_kernel(const float* __restrict__ y_pred,
                        const float* __restrict__ y_true,
                        const float* __restrict__ x,
                        const int* __restrict__ fidx,
                        float* __restrict__ out,
                        int B, int N, float inv_B) {
    const int lane   = threadIdx.x & 31;
    const int gwarp  = blockIdx.x * WPB + (threadIdx.x >> 5);
    const int nwarps = gridDim.x * WPB;

    const float4* __restrict__ x4 = (const float4*)x;

    for (int r = gwarp; r < B; r += nwarps) {
        int idx = fidx[r];
        idx = min(max(idx, 0), N - 1);
        const int nc = idx >> 2;   // clean interior float4 vectors

        const float* __restrict__ p = y_pred + (size_t)r * N;
        const float* __restrict__ t = y_true + (size_t)r * N;
        const float4* __restrict__ p4 = (const float4*)p;
        const float4* __restrict__ t4 = (const float4*)t;

        float acc = 0.0f;

        // Interior loop: lane-strided float4, unrolled for deep MLP.
        #pragma unroll 8
        for (int v = lane; v < nc; v += 32) {
            const int j0 = v << 2;
            float4 a  = p4[v];
            float4 b  = t4[v];
            float4 xv = x4[v];                 // x[j0..j0+3] (L1-resident)
            float xm1 = x[j0 ? (j0 - 1) : 0];  // clamp: j0==0 -> x[0]
            float xp4 = x[j0 + 4];             // safe: j0+4 <= idx <= N-1

            acc = fmaf(0.5f * (xv.y - xm1),  a.x - b.x, acc);
            acc = fmaf(0.5f * (xv.z - xv.x), a.y - b.y, acc);
            acc = fmaf(0.5f * (xv.w - xv.y), a.z - b.z, acc);
            acc = fmaf(0.5f * (xp4  - xv.z), a.w - b.w, acc);
        }

        // Boundary tail: elements [4*nc, idx] (at most 4), lanes cover them.
        for (int j = (nc << 2) + lane; j <= idx; j += 32) {
            float left  = (j > 0)   ? (x[j] - x[j - 1]) : 0.0f;
            float right = (j < idx) ? (x[j + 1] - x[j]) : 0.0f;
            acc = fmaf(0.5f * (left + right), p[j] - t[j], acc);
        }

        // Warp reduction (shuffle only)
        #pragma unroll
        for (int off = 16; off > 0; off >>= 1)
            acc += __shfl_xor_sync(0xFFFFFFFFu, acc, off);

        if (lane == 0)
            atomicAdd(out, acc * acc * inv_B);   // err_sq pre-scaled by 1/B
    }
}

extern "C" void kernel_launch(void* const* d_in, const int* in_sizes, int n_in,
                              void* d_out, int out_size) {
    const float* y_pred = (const float*)d_in[0];
    const float* y_true = (const float*)d_in[1];
    const float* x_vals = (const float*)d_in[2];
    const int*   fidx   = (const int*)d_in[3];
    float* out = (float*)d_out;

    const int B = in_sizes[3];   // fracture_idx element count
    const int N = in_sizes[2];   // x_values element count

    const int grid = (B + WPB - 1) / WPB;   // one warp per row, single wave

    zero_out_kernel<<<1, 1>>>(out);
    strain_loss_kernel<<<grid, THREADS>>>(y_pred, y_true, x_vals, fidx, out,
                                          B, N, 1.0f / (float)B);
}

// round 10
// speedup vs baseline: 1.3664x; 1.3664x over previous
#include <cuda_runtime.h>

// CustomStrainEnergyLoss: mean over B of (trapz(y_pred - y_true, x, segments j < idx))^2
// Element-weight form: integral = sum_{j=0}^{idx} w(j) * (p[j]-t[j]),
//   w(j) = 0.5*((j>0 ? x[j]-x[j-1] : 0) + (j<idx ? x[j+1]-x[j] : 0))
// Interior j (all lanes of vectors v < idx>>2 have j < idx, j-1 >= -1):
//   w(j) = 0.5*(x[j+1]-x[max(j-1,0)])   (clamp makes the j=0 weight exact).
//
// Block-per-row + explicit dual-batched float4 loads (6 independent LDG.128
// per thread before any FMA -> deep MLP) + 128-thread blocks for CTA overlap.
// No __device__ globals, no prep pass (weights from L1-resident x inline).

#define THREADS 128

__global__ void zero_out_kernel(float* out) {
    out[0] = 0.0f;
}

__device__ __forceinline__ float dot4(const float4 a, const float4 b,
                                      const float4 xv, float xm1, float xp4,
                                      float& acc0, float& acc1) {
    acc0 = fmaf(0.5f * (xv.y - xm1),  a.x - b.x, acc0);
    acc1 = fmaf(0.5f * (xv.z - xv.x), a.y - b.y, acc1);
    acc0 = fmaf(0.5f * (xv.w - xv.y), a.z - b.z, acc0);
    acc1 = fmaf(0.5f * (xp4  - xv.z), a.w - b.w, acc1);
    return acc0;
}

__global__ __launch_bounds__(THREADS)
void strain_loss_kernel(const float* __restrict__ y_pred,
                        const float* __restrict__ y_true,
                        const float* __restrict__ x,
                        const int* __restrict__ fidx,
                        float* __restrict__ out,
                        int N, float inv_B) {
    const int r = blockIdx.x;
    int idx = fidx[r];
    idx = min(max(idx, 0), N - 1);
    const int nc = idx >> 2;   // clean interior float4 vectors (all lanes j < idx)

    const float* __restrict__ p = y_pred + (size_t)r * N;
    const float* __restrict__ t = y_true + (size_t)r * N;
    const float4* __restrict__ p4 = (const float4*)p;
    const float4* __restrict__ t4 = (const float4*)t;
    const float4* __restrict__ x4 = (const float4*)x;

    float acc0 = 0.0f, acc1 = 0.0f;

    // Dual-batched interior: issue 6 independent LDG.128 (+4 L1-hit scalars)
    // before consuming anything.
    int v = threadIdx.x;
    for (; v + THREADS < nc; v += 2 * THREADS) {
        const int va = v, vb = v + THREADS;
        const int ja = va << 2, jb = vb << 2;

        float4 a0 = p4[va];
        float4 b0 = t4[va];
        float4 a1 = p4[vb];
        float4 b1 = t4[vb];
        float4 xv0 = x4[va];
        float4 xv1 = x4[vb];
        float xm1a = x[ja ? (ja - 1) : 0];
        float xp4a = x[ja + 4];              // ja+4 <= idx <= N-1, safe
        float xm1b = x[jb - 1];
        float xp4b = x[jb + 4];

        dot4(a0, b0, xv0, xm1a, xp4a, acc0, acc1);
        dot4(a1, b1, xv1, xm1b, xp4b, acc0, acc1);
    }
    if (v < nc) {
        const int j0 = v << 2;
        float4 a0 = p4[v];
        float4 b0 = t4[v];
        float4 xv = x4[v];
        float xm1 = x[j0 ? (j0 - 1) : 0];
        float xp4 = x[j0 + 4];
        dot4(a0, b0, xv, xm1, xp4, acc0, acc1);
    }

    float acc = acc0 + acc1;

    // Scalar tail: elements [4*nc, idx] (at most 4), exact trapezoid weights.
    for (int j = (nc << 2) + threadIdx.x; j <= idx; j += THREADS) {
        float left  = (j > 0)   ? (x[j] - x[j - 1]) : 0.0f;
        float right = (j < idx) ? (x[j + 1] - x[j]) : 0.0f;
        acc = fmaf(0.5f * (left + right), p[j] - t[j], acc);
    }

    // Block reduction: warp shuffle then shared memory (4 warps)
    #pragma unroll
    for (int off = 16; off > 0; off >>= 1)
        acc += __shfl_xor_sync(0xFFFFFFFFu, acc, off);

    __shared__ float warp_sums[THREADS / 32];
    const int lane = threadIdx.x & 31;
    const int wid  = threadIdx.x >> 5;
    if (lane == 0) warp_sums[wid] = acc;
    __syncthreads();

    if (wid == 0) {
        float s = (lane < THREADS / 32) ? warp_sums[lane] : 0.0f;
        #pragma unroll
        for (int off = 2; off > 0; off >>= 1)
            s += __shfl_xor_sync(0xFFFFFFFFu, s, off);
        if (lane == 0)
            atomicAdd(out, s * s * inv_B);   // err_sq pre-scaled by 1/B
    }
}

extern "C" void kernel_launch(void* const* d_in, const int* in_sizes, int n_in,
                              void* d_out, int out_size) {
    const float* y_pred = (const float*)d_in[0];
    const float* y_true = (const float*)d_in[1];
    const float* x_vals = (const float*)d_in[2];
    const int*   fidx   = (const int*)d_in[3];
    float* out = (float*)d_out;

    const int B = in_sizes[3];   // fracture_idx element count
    const int N = in_sizes[2];   // x_values element count

    zero_out_kernel<<<1, 1>>>(out);
    strain_loss_kernel<<<B, THREADS>>>(y_pred, y_true, x_vals, fidx, out,
                                       N, 1.0f / (float)B);
}